// round 3
// baseline (speedup 1.0000x reference)
#include <cuda_runtime.h>

#define DIM      128
#define KCODES   1024
#define TM       128     // rows per block
#define TK       64      // codes per smem tile
#define PAD      132     // smem row pitch in floats (16B-aligned rows, conflict-light)
#define NTHREADS 256

__device__ float g_e2[KCODES];

// ---------------------------------------------------------------------------
// e2[k] = sum_d embed[k][d]^2
// ---------------------------------------------------------------------------
__global__ void e2_kernel(const float* __restrict__ embed) {
    int k = blockIdx.x * blockDim.x + threadIdx.x;
    if (k < KCODES) {
        const float* e = embed + (size_t)k * DIM;
        float s = 0.f;
#pragma unroll 16
        for (int d = 0; d < DIM; d++) s = fmaf(e[d], e[d], s);
        g_e2[k] = s;
    }
}

// Packed dual FMA: acc.{lo,hi} += a.{lo,hi} * b.{lo,hi}   (FFMA2 on sm_103a)
__device__ __forceinline__ void ffma2(unsigned long long& acc,
                                      unsigned long long a,
                                      unsigned long long b) {
    asm("fma.rn.f32x2 %0, %1, %2, %0;" : "+l"(acc) : "l"(a), "l"(b));
}

// ---------------------------------------------------------------------------
// Main VQ kernel: per block, 128 rows vs all 1024 codes (16 tiles of 64).
// Accumulators pack (d even, d odd) partial sums in one 64-bit reg; both
// operands load as natural LDS.64 — no packing MOVs.
// ---------------------------------------------------------------------------
__global__ __launch_bounds__(NTHREADS, 2)
void vq_kernel(const float* __restrict__ x, const float* __restrict__ embed,
               float* __restrict__ out_q, float* __restrict__ out_idx, int nrows)
{
    extern __shared__ float smem[];
    float* xs   = smem;                              // [TM][PAD]
    float* es   = smem + TM * PAD;                   // [TK][PAD]
    float* e2s  = smem + TM * PAD + TK * PAD;        // [TK]
    int*   fIdx = (int*)(e2s + TK);                  // [TM]

    const int tid = threadIdx.x;
    const int tx = tid & 15;        // code lane (codes tx + 16*j)
    const int ty = tid >> 4;        // row lane  (rows  ty + 16*i)
    const int rowbase = blockIdx.x * TM;

    // ---- load x tile (coalesced float4, conflict-free STS) ----
    for (int i = tid; i < TM * (DIM / 4); i += NTHREADS) {
        int r = i >> 5, c4 = (i & 31) << 2;
        int rg = rowbase + r; if (rg >= nrows) rg = nrows - 1;
        float4 v = *(const float4*)(x + (size_t)rg * DIM + c4);
        *(float4*)(xs + r * PAD + c4) = v;
    }

    float bestv[8]; int besti[8];
#pragma unroll
    for (int i = 0; i < 8; i++) { bestv[i] = -3.4e38f; besti[i] = 0; }

    const float* xb = xs + ty * PAD;
    const float* eb = es + tx * PAD;

    for (int kt = 0; kt < KCODES / TK; kt++) {
        __syncthreads();   // previous tile fully consumed
        for (int i = tid; i < TK * (DIM / 4); i += NTHREADS) {
            int r = i >> 5, c4 = (i & 31) << 2;
            float4 v = *(const float4*)(embed + (size_t)(kt * TK + r) * DIM + c4);
            *(float4*)(es + r * PAD + c4) = v;
        }
        if (tid < TK) e2s[tid] = g_e2[kt * TK + tid];
        __syncthreads();

        unsigned long long acc[8][4];
#pragma unroll
        for (int i = 0; i < 8; i++)
#pragma unroll
            for (int j = 0; j < 4; j++) acc[i][j] = 0ull;

#pragma unroll 4
        for (int d = 0; d < DIM; d += 2) {
            unsigned long long xf[8], ef[4];
#pragma unroll
            for (int i = 0; i < 8; i++)
                xf[i] = *(const unsigned long long*)(xb + (16 * i) * PAD + d);
#pragma unroll
            for (int j = 0; j < 4; j++)
                ef[j] = *(const unsigned long long*)(eb + (16 * j) * PAD + d);
#pragma unroll
            for (int i = 0; i < 8; i++)
#pragma unroll
                for (int j = 0; j < 4; j++) ffma2(acc[i][j], xf[i], ef[j]);
        }

        // fold the (even,odd) partials, score, keep running argmax
#pragma unroll
        for (int j = 0; j < 4; j++) {
            int cl  = tx + 16 * j;
            float e2v = e2s[cl];
            int c = kt * TK + cl;
#pragma unroll
            for (int i = 0; i < 8; i++) {
                unsigned long long a = acc[i][j];
                float lo = __uint_as_float((unsigned)a);
                float hi = __uint_as_float((unsigned)(a >> 32));
                float val = 2.0f * (lo + hi) - e2v;
                if (val > bestv[i]) { bestv[i] = val; besti[i] = c; }  // strict >: first max wins
            }
        }
    }

    // ---- cross-thread argmax reduction per row ----
    __syncthreads();
    float* redv = es;                       // reuse es region: [TM][17]
    int*   redi = (int*)(es + TM * 17);
#pragma unroll
    for (int i = 0; i < 8; i++) {
        int r = ty + 16 * i;
        redv[r * 17 + tx] = bestv[i];
        redi[r * 17 + tx] = besti[i];
    }
    __syncthreads();
    if (tid < TM) {
        int r = tid;
        float bv = redv[r * 17]; int bi = redi[r * 17];
#pragma unroll
        for (int t = 1; t < 16; t++) {
            float v = redv[r * 17 + t]; int ii = redi[r * 17 + t];
            if (v > bv || (v == bv && ii < bi)) { bv = v; bi = ii; }
        }
        fIdx[r] = bi;
        if (out_idx != nullptr && rowbase + r < nrows)
            out_idx[rowbase + r] = (float)bi;
    }
    __syncthreads();

    // ---- gather: quantize = embed[idx]  (bitwise-exact copy, embed is L2-hot) ----
    for (int i = tid; i < TM * (DIM / 4); i += NTHREADS) {
        int r = i >> 5, c4 = (i & 31) << 2;
        if (rowbase + r < nrows) {
            float4 v = *(const float4*)(embed + (size_t)fIdx[r] * DIM + c4);
            *(float4*)(out_q + (size_t)(rowbase + r) * DIM + c4) = v;
        }
    }
}

__global__ void fill_kernel(float* p, long long n) {
    long long i = (long long)blockIdx.x * blockDim.x + threadIdx.x;
    if (i < n) p[i] = 0.f;
}

extern "C" void kernel_launch(void* const* d_in, const int* in_sizes, int n_in,
                              void* d_out, int out_size) {
    // x is the big tensor, embed is [1024,128] — identify by size defensively.
    int xi = 0, ei = 1;
    if (n_in >= 2 && in_sizes[1] > in_sizes[0]) { xi = 1; ei = 0; }
    const float* x     = (const float*)d_in[xi];
    const float* embed = (const float*)d_in[ei];
    int nrows = in_sizes[xi] / DIM;

    float* out_q = (float*)d_out;
    long long ND = (long long)nrows * DIM;
    bool widx = ((long long)out_size >= ND + nrows);
    float* out_idx = widx ? out_q + ND : nullptr;

    e2_kernel<<<(KCODES + 255) / 256, 256>>>(embed);

    int smem_bytes = (TM * PAD + TK * PAD + TK + TM) * 4;
    cudaFuncSetAttribute(vq_kernel, cudaFuncAttributeMaxDynamicSharedMemorySize, smem_bytes);
    vq_kernel<<<(nrows + TM - 1) / TM, NTHREADS, smem_bytes>>>(x, embed, out_q, out_idx, nrows);

    long long covered = ND + (widx ? nrows : 0);
    long long tail = (long long)out_size - covered;
    if (tail > 0)
        fill_kernel<<<(int)((tail + 255) / 256), 256>>>(out_q + covered, tail);
}

// round 6
// speedup vs baseline: 1.3589x; 1.3589x over previous
#include <cuda_runtime.h>
#include <cuda_fp16.h>
#include <cstdint>
#include <cfloat>

#define DIM      128
#define K2       256                 // halfs per row: [hi(128) | lo(128)]
#define KCODES   1024
#define TM       128                 // rows per CTA
#define SUBN     32                  // codes per subtile
#define NSUB     (KCODES / SUBN)
#define NTHREADS 256

// ---- smem byte offsets ----
#define SM_A     0                   // 128 rows x 512B (swizzled)      = 65536
#define SM_B0    65536               // 32 rows x 512B                  = 16384
#define SM_B1    81920               //                                 = 16384
#define SM_E2    98304               // 1024 floats                     = 4096
#define SM_REDV  102400              // 128*8 floats                    = 4096
#define SM_REDI  106496              // 128*8 ints                      = 4096
#define SM_FIDX  110592              // 128 ints                        = 512
#define SMEM_TOTAL 111104

__device__ float  g_e2[KCODES];
__device__ __half g_esplit[KCODES * K2];   // per code: [eh(128) | el(128)]

// ---------------------------------------------------------------- helpers
__device__ __forceinline__ uint32_t smem_u32(const void* p) {
    uint32_t a;
    asm("{ .reg .u64 t; cvta.to.shared.u64 t, %1; cvt.u32.u64 %0, t; }" : "=r"(a) : "l"(p));
    return a;
}
// swizzled byte offset: row-major 512B rows, 16B chunks XOR'd by row&7
__device__ __forceinline__ uint32_t sw_off(int row, int chunk) {
    return (uint32_t)(row * 512) + (uint32_t)(((chunk ^ (row & 7)) << 4));
}
__device__ __forceinline__ void ldsm4(uint32_t* r, uint32_t a) {
    asm volatile("ldmatrix.sync.aligned.m8n8.x4.shared.b16 {%0,%1,%2,%3}, [%4];"
                 : "=r"(r[0]), "=r"(r[1]), "=r"(r[2]), "=r"(r[3]) : "r"(a));
}
__device__ __forceinline__ void mma16816(float* c, const uint32_t* a, uint32_t b0, uint32_t b1) {
    asm volatile("mma.sync.aligned.m16n8k16.row.col.f32.f16.f16.f32 "
                 "{%0,%1,%2,%3}, {%4,%5,%6,%7}, {%8,%9}, {%0,%1,%2,%3};"
                 : "+f"(c[0]), "+f"(c[1]), "+f"(c[2]), "+f"(c[3])
                 : "r"(a[0]), "r"(a[1]), "r"(a[2]), "r"(a[3]), "r"(b0), "r"(b1));
}
__device__ __forceinline__ void cp16(uint32_t dst, const void* src) {
    asm volatile("cp.async.cg.shared.global [%0], [%1], 16;"
                 :: "r"(dst), "l"(__cvta_generic_to_global(src)) : "memory");
}
__device__ __forceinline__ void cp_commit() { asm volatile("cp.async.commit_group;" ::: "memory"); }
__device__ __forceinline__ void cp_wait1()  { asm volatile("cp.async.wait_group 1;" ::: "memory"); }
__device__ __forceinline__ void cp_wait0()  { asm volatile("cp.async.wait_group 0;" ::: "memory"); }

// ---------------------------------------------------------------- prep
__global__ void e2_kernel(const float* __restrict__ embed) {
    int k = blockIdx.x * blockDim.x + threadIdx.x;
    if (k < KCODES) {
        const float* e = embed + (size_t)k * DIM;
        float s = 0.f;
#pragma unroll 16
        for (int d = 0; d < DIM; d++) s = fmaf(e[d], e[d], s);
        g_e2[k] = s;
    }
}
// segment split: row k -> [eh(0..127) | el(0..127)]
__global__ void split_kernel(const float* __restrict__ embed) {
    int i = blockIdx.x * blockDim.x + threadIdx.x;
    if (i < KCODES * DIM) {
        int k = i >> 7, d = i & 127;
        float v = embed[i];
        __half h = __float2half_rn(v);
        __half l = __float2half_rn(v - __half2float(h));
        g_esplit[(size_t)k * K2 + d]       = h;
        g_esplit[(size_t)k * K2 + 128 + d] = l;
    }
}

// ---------------------------------------------------------------- main
__global__ __launch_bounds__(NTHREADS, 2)
void vq_mma_kernel(const float* __restrict__ x, const float* __restrict__ embed,
                   float* __restrict__ out_q, float* __restrict__ out_idx, int nrows)
{
    extern __shared__ char smem[];
    const uint32_t sb = smem_u32(smem);
    const int tid  = threadIdx.x;
    const int w    = tid >> 5;
    const int l    = tid & 31;
    const int rowbase = blockIdx.x * TM;

    // e2 -> smem
    float* e2s = (float*)(smem + SM_E2);
    for (int i = tid; i < KCODES; i += NTHREADS) e2s[i] = g_e2[i];

    // ---- A tile: load x, fp16 hi/lo split into segments, swizzled store ----
    // chunk c (0..15) = dims 8c..8c+7 of hi; chunk c+16 = same dims of lo
#pragma unroll 2
    for (int it = 0; it < 8; it++) {
        int i = tid + it * NTHREADS;          // 0..2047
        int r = i >> 4, c = i & 15;           // row, dim-chunk (8 dims)
        int rg = rowbase + r; if (rg >= nrows) rg = nrows - 1;
        const float* xp = x + (size_t)rg * DIM + c * 8;
        float4 v0 = *(const float4*)(xp);
        float4 v1 = *(const float4*)(xp + 4);
        __half h0 = __float2half_rn(v0.x), h1 = __float2half_rn(v0.y),
               h2 = __float2half_rn(v0.z), h3 = __float2half_rn(v0.w),
               h4 = __float2half_rn(v1.x), h5 = __float2half_rn(v1.y),
               h6 = __float2half_rn(v1.z), h7 = __float2half_rn(v1.w);
        __half2 hi01 = __halves2half2(h0, h1), hi23 = __halves2half2(h2, h3);
        __half2 hi45 = __halves2half2(h4, h5), hi67 = __halves2half2(h6, h7);
        __half2 lo01 = __halves2half2(__float2half_rn(v0.x - __half2float(h0)),
                                      __float2half_rn(v0.y - __half2float(h1)));
        __half2 lo23 = __halves2half2(__float2half_rn(v0.z - __half2float(h2)),
                                      __float2half_rn(v0.w - __half2float(h3)));
        __half2 lo45 = __halves2half2(__float2half_rn(v1.x - __half2float(h4)),
                                      __float2half_rn(v1.y - __half2float(h5)));
        __half2 lo67 = __halves2half2(__float2half_rn(v1.z - __half2float(h6)),
                                      __float2half_rn(v1.w - __half2float(h7)));
        uint4 hk = make_uint4(*(uint32_t*)&hi01, *(uint32_t*)&hi23,
                              *(uint32_t*)&hi45, *(uint32_t*)&hi67);
        uint4 lk = make_uint4(*(uint32_t*)&lo01, *(uint32_t*)&lo23,
                              *(uint32_t*)&lo45, *(uint32_t*)&lo67);
        *(uint4*)(smem + SM_A + sw_off(r, c))      = hk;
        *(uint4*)(smem + SM_A + sw_off(r, c + 16)) = lk;
    }

    // ---- prefetch B subtile 0 (rows already [eh|el] segmented in gmem) ----
    {
        const uint32_t b0 = sb + SM_B0;
#pragma unroll
        for (int k = 0; k < 4; k++) {
            int id = tid + k * NTHREADS;       // 0..1023 chunks (32 rows x 32)
            int r = id >> 5, ci = id & 31;
            cp16(b0 + sw_off(r, ci), g_esplit + (size_t)r * K2 + ci * 8);
        }
        cp_commit();
    }

    // per-warp geometry
    const int colhalf = w >> 2;               // 0/1: cols 0-15 / 16-31 of subtile
    const int mrow0   = (w & 3) * 32;         // rows of this warp
    const int arow_l  = (l & 15);
    const int ag      = (l >> 4);             // 0/1 -> k-chunk offset
    const int brow    = colhalf * 16 + ((l >> 4) << 3) + (l & 7);
    const int bg      = (l >> 3) & 1;

    float bestv[4]; int besti[4];
#pragma unroll
    for (int i = 0; i < 4; i++) { bestv[i] = -FLT_MAX; besti[i] = 0; }

    for (int s = 0; s < NSUB; s++) {
        // prefetch next subtile into the other buffer
        if (s + 1 < NSUB) {
            const uint32_t bn = sb + (((s + 1) & 1) ? SM_B1 : SM_B0);
#pragma unroll
            for (int k = 0; k < 4; k++) {
                int id = tid + k * NTHREADS;
                int r = id >> 5, ci = id & 31;
                cp16(bn + sw_off(r, ci),
                     g_esplit + ((size_t)(s + 1) * SUBN + r) * K2 + ci * 8);
            }
            cp_commit();
            cp_wait1();
        } else {
            cp_wait0();
        }
        __syncthreads();   // subtile s visible to all; prior compute done before overwrite

        const uint32_t bbase = sb + ((s & 1) ? SM_B1 : SM_B0);

        float c[2][2][4];
#pragma unroll
        for (int mt = 0; mt < 2; mt++)
#pragma unroll
            for (int nt = 0; nt < 2; nt++)
#pragma unroll
                for (int i = 0; i < 4; i++) c[mt][nt][i] = 0.f;

        // 3-term split: xh*eh + xl*eh + xh*el  (xl*el ~ 2^-22, dropped)
#pragma unroll
        for (int pass = 0; pass < 3; pass++) {
            const int aso = (pass == 1) ? 16 : 0;   // A: xl segment on pass 1
            const int bso = (pass == 2) ? 16 : 0;   // B: el segment on pass 2
#pragma unroll
            for (int kt = 0; kt < 8; kt++) {
                uint32_t aF0[4], aF1[4], bF[4];
                int ck = kt * 2;
                ldsm4(aF0, sb + SM_A + sw_off(mrow0 + arow_l,      aso + ck + ag));
                ldsm4(aF1, sb + SM_A + sw_off(mrow0 + 16 + arow_l, aso + ck + ag));
                ldsm4(bF, bbase + sw_off(brow, bso + ck + bg));
                mma16816(c[0][0], aF0, bF[0], bF[1]);
                mma16816(c[0][1], aF0, bF[2], bF[3]);
                mma16816(c[1][0], aF1, bF[0], bF[1]);
                mma16816(c[1][1], aF1, bF[2], bF[3]);
            }
        }

        // ---- score + running argmax (ascending col => first max wins) ----
        {
            int col0 = s * SUBN + colhalf * 16 + (l & 3) * 2;
            float2 eA = *(const float2*)(e2s + col0);
            float2 eB = *(const float2*)(e2s + col0 + 8);
#pragma unroll
            for (int mt = 0; mt < 2; mt++)
#pragma unroll
                for (int hh = 0; hh < 2; hh++) {
                    int sl = mt * 2 + hh;
                    float v0 = fmaf(2.f, c[mt][0][hh * 2 + 0], -eA.x);
                    float v1 = fmaf(2.f, c[mt][0][hh * 2 + 1], -eA.y);
                    float v2 = fmaf(2.f, c[mt][1][hh * 2 + 0], -eB.x);
                    float v3 = fmaf(2.f, c[mt][1][hh * 2 + 1], -eB.y);
                    if (v0 > bestv[sl]) { bestv[sl] = v0; besti[sl] = col0; }
                    if (v1 > bestv[sl]) { bestv[sl] = v1; besti[sl] = col0 + 1; }
                    if (v2 > bestv[sl]) { bestv[sl] = v2; besti[sl] = col0 + 8; }
                    if (v3 > bestv[sl]) { bestv[sl] = v3; besti[sl] = col0 + 9; }
                }
        }
        __syncthreads();   // compute done before next prefetch overwrites this buffer
    }

    // ---- cross-warp/lane argmax reduction ----
    float* redv = (float*)(smem + SM_REDV);
    int*   redi = (int*)(smem + SM_REDI);
    int*   fIdx = (int*)(smem + SM_FIDX);
#pragma unroll
    for (int mt = 0; mt < 2; mt++)
#pragma unroll
        for (int hh = 0; hh < 2; hh++) {
            int sl  = mt * 2 + hh;
            int row = mrow0 + mt * 16 + hh * 8 + (l >> 2);
            int cd  = colhalf * 4 + (l & 3);
            redv[row * 8 + cd] = bestv[sl];
            redi[row * 8 + cd] = besti[sl];
        }
    __syncthreads();
    if (tid < TM) {
        float bv = redv[tid * 8]; int bi = redi[tid * 8];
#pragma unroll
        for (int cd = 1; cd < 8; cd++) {
            float v = redv[tid * 8 + cd]; int ii = redi[tid * 8 + cd];
            if (v > bv || (v == bv && ii < bi)) { bv = v; bi = ii; }
        }
        fIdx[tid] = bi;
        int rg = rowbase + tid;
        if (out_idx != nullptr && rg < nrows) out_idx[rg] = (float)bi;
    }
    __syncthreads();

    // ---- gather: quantize = embed[idx] (bitwise-exact fp32 copy) ----
    for (int i = tid; i < TM * (DIM / 4); i += NTHREADS) {
        int r = i >> 5, c4 = (i & 31) << 2;
        int rg = rowbase + r;
        if (rg < nrows) {
            float4 v = *(const float4*)(embed + (size_t)fIdx[r] * DIM + c4);
            *(float4*)(out_q + (size_t)rg * DIM + c4) = v;
        }
    }
}

__global__ void fill_kernel(float* p, long long n) {
    long long i = (long long)blockIdx.x * blockDim.x + threadIdx.x;
    if (i < n) p[i] = 0.f;
}

// ---------------------------------------------------------------- launch
extern "C" void kernel_launch(void* const* d_in, const int* in_sizes, int n_in,
                              void* d_out, int out_size) {
    int xi = 0, ei = 1;
    if (n_in >= 2 && in_sizes[1] > in_sizes[0]) { xi = 1; ei = 0; }
    const float* x     = (const float*)d_in[xi];
    const float* embed = (const float*)d_in[ei];
    int nrows = in_sizes[xi] / DIM;

    float* out_q = (float*)d_out;
    long long ND = (long long)nrows * DIM;
    bool widx = ((long long)out_size >= ND + nrows);
    float* out_idx = widx ? out_q + ND : nullptr;

    e2_kernel<<<(KCODES + 255) / 256, 256>>>(embed);
    split_kernel<<<(KCODES * DIM + 255) / 256, 256>>>(embed);

    cudaFuncSetAttribute(vq_mma_kernel, cudaFuncAttributeMaxDynamicSharedMemorySize, SMEM_TOTAL);
    vq_mma_kernel<<<(nrows + TM - 1) / TM, NTHREADS, SMEM_TOTAL>>>(x, embed, out_q, out_idx, nrows);

    long long covered = ND + (widx ? nrows : 0);
    long long tail = (long long)out_size - covered;
    if (tail > 0)
        fill_kernel<<<(int)((tail + 255) / 256), 256>>>(out_q + covered, tail);
}

// round 7
// speedup vs baseline: 3.1085x; 2.2875x over previous
#include <cuda_runtime.h>
#include <cuda_fp16.h>
#include <cstdint>
#include <cfloat>

#define DIM      128
#define K2       256                 // halfs per row: [hi(128) | lo(128)]
#define KCODES   1024
#define TM       128                 // rows per CTA
#define SUBN     32                  // codes per subtile
#define NSUB     (KCODES / SUBN)
#define NTHREADS 256

// ---- smem byte offsets ----
#define SM_A     0                   // 128 rows x 512B (swizzled)      = 65536
#define SM_B0    65536               // 32 rows x 512B                  = 16384
#define SM_B1    81920               //                                 = 16384
#define SM_E2    98304               // 1024 floats                     = 4096
#define SM_REDV  102400              // 128*8 floats                    = 4096
#define SM_REDI  106496              // 128*8 ints                      = 4096
#define SM_FIDX  110592              // 128 ints                        = 512
#define SMEM_TOTAL 111104

__device__ float  g_e2[KCODES];
__device__ __half g_esplit[KCODES * K2];   // per code: [eh(128) | el(128)]

// ---------------------------------------------------------------- helpers
__device__ __forceinline__ uint32_t smem_u32(const void* p) {
    uint32_t a;
    asm("{ .reg .u64 t; cvta.to.shared.u64 t, %1; cvt.u32.u64 %0, t; }" : "=r"(a) : "l"(p));
    return a;
}
// swizzled byte offset: row-major 512B rows, 16B chunks XOR'd by row&7
__device__ __forceinline__ uint32_t sw_off(int row, int chunk) {
    return (uint32_t)(row * 512) + (uint32_t)(((chunk ^ (row & 7)) << 4));
}
__device__ __forceinline__ void ldsm4(uint32_t* r, uint32_t a) {
    asm volatile("ldmatrix.sync.aligned.m8n8.x4.shared.b16 {%0,%1,%2,%3}, [%4];"
                 : "=r"(r[0]), "=r"(r[1]), "=r"(r[2]), "=r"(r[3]) : "r"(a));
}
__device__ __forceinline__ void mma16816(float* c, const uint32_t* a, uint32_t b0, uint32_t b1) {
    asm volatile("mma.sync.aligned.m16n8k16.row.col.f32.f16.f16.f32 "
                 "{%0,%1,%2,%3}, {%4,%5,%6,%7}, {%8,%9}, {%0,%1,%2,%3};"
                 : "+f"(c[0]), "+f"(c[1]), "+f"(c[2]), "+f"(c[3])
                 : "r"(a[0]), "r"(a[1]), "r"(a[2]), "r"(a[3]), "r"(b0), "r"(b1));
}
__device__ __forceinline__ void cp16(uint32_t dst, const void* src) {
    asm volatile("cp.async.cg.shared.global [%0], [%1], 16;"
                 :: "r"(dst), "l"(__cvta_generic_to_global(src)) : "memory");
}
__device__ __forceinline__ void cp_commit() { asm volatile("cp.async.commit_group;" ::: "memory"); }
__device__ __forceinline__ void cp_wait1()  { asm volatile("cp.async.wait_group 1;" ::: "memory"); }
__device__ __forceinline__ void cp_wait0()  { asm volatile("cp.async.wait_group 0;" ::: "memory"); }

// ---------------------------------------------------------------- prep
// One warp per code: lane-parallel e2 (shuffle reduce) + fp16 hi/lo split.
__global__ void prep_kernel(const float* __restrict__ embed) {
    int gw   = (blockIdx.x * blockDim.x + threadIdx.x) >> 5;   // code id
    int lane = threadIdx.x & 31;
    if (gw >= KCODES) return;
    float4 v = *(const float4*)(embed + (size_t)gw * DIM + lane * 4);
    float s = fmaf(v.x, v.x, fmaf(v.y, v.y, fmaf(v.z, v.z, v.w * v.w)));
#pragma unroll
    for (int o = 16; o; o >>= 1) s += __shfl_xor_sync(0xFFFFFFFFu, s, o);
    if (lane == 0) g_e2[gw] = s;

    __half h0 = __float2half_rn(v.x), h1 = __float2half_rn(v.y),
           h2 = __float2half_rn(v.z), h3 = __float2half_rn(v.w);
    __half2 hiA = __halves2half2(h0, h1), hiB = __halves2half2(h2, h3);
    __half2 loA = __halves2half2(__float2half_rn(v.x - __half2float(h0)),
                                 __float2half_rn(v.y - __half2float(h1)));
    __half2 loB = __halves2half2(__float2half_rn(v.z - __half2float(h2)),
                                 __float2half_rn(v.w - __half2float(h3)));
    uint2 hk = make_uint2(*(uint32_t*)&hiA, *(uint32_t*)&hiB);
    uint2 lk = make_uint2(*(uint32_t*)&loA, *(uint32_t*)&loB);
    *(uint2*)(g_esplit + (size_t)gw * K2 + lane * 4)       = hk;
    *(uint2*)(g_esplit + (size_t)gw * K2 + 128 + lane * 4) = lk;
}

// ---------------------------------------------------------------- main
__global__ __launch_bounds__(NTHREADS, 2)
void vq_mma_kernel(const float* __restrict__ x, const float* __restrict__ embed,
                   float* __restrict__ out_q, float* __restrict__ out_idx, int nrows)
{
    extern __shared__ char smem[];
    const uint32_t sb = smem_u32(smem);
    const int tid  = threadIdx.x;
    const int w    = tid >> 5;
    const int l    = tid & 31;
    const int rowbase = blockIdx.x * TM;

    // e2 -> smem
    float* e2s = (float*)(smem + SM_E2);
    for (int i = tid; i < KCODES; i += NTHREADS) e2s[i] = g_e2[i];

    // ---- A tile: load x, fp16 hi/lo split into segments, swizzled store ----
    // chunk c (0..15) = dims 8c..8c+7 of hi; chunk c+16 = same dims of lo
#pragma unroll 2
    for (int it = 0; it < 8; it++) {
        int i = tid + it * NTHREADS;          // 0..2047
        int r = i >> 4, c = i & 15;           // row, dim-chunk (8 dims)
        int rg = rowbase + r; if (rg >= nrows) rg = nrows - 1;
        const float* xp = x + (size_t)rg * DIM + c * 8;
        float4 v0 = *(const float4*)(xp);
        float4 v1 = *(const float4*)(xp + 4);
        __half h0 = __float2half_rn(v0.x), h1 = __float2half_rn(v0.y),
               h2 = __float2half_rn(v0.z), h3 = __float2half_rn(v0.w),
               h4 = __float2half_rn(v1.x), h5 = __float2half_rn(v1.y),
               h6 = __float2half_rn(v1.z), h7 = __float2half_rn(v1.w);
        __half2 hi01 = __halves2half2(h0, h1), hi23 = __halves2half2(h2, h3);
        __half2 hi45 = __halves2half2(h4, h5), hi67 = __halves2half2(h6, h7);
        __half2 lo01 = __halves2half2(__float2half_rn(v0.x - __half2float(h0)),
                                      __float2half_rn(v0.y - __half2float(h1)));
        __half2 lo23 = __halves2half2(__float2half_rn(v0.z - __half2float(h2)),
                                      __float2half_rn(v0.w - __half2float(h3)));
        __half2 lo45 = __halves2half2(__float2half_rn(v1.x - __half2float(h4)),
                                      __float2half_rn(v1.y - __half2float(h5)));
        __half2 lo67 = __halves2half2(__float2half_rn(v1.z - __half2float(h6)),
                                      __float2half_rn(v1.w - __half2float(h7)));
        uint4 hk = make_uint4(*(uint32_t*)&hi01, *(uint32_t*)&hi23,
                              *(uint32_t*)&hi45, *(uint32_t*)&hi67);
        uint4 lk = make_uint4(*(uint32_t*)&lo01, *(uint32_t*)&lo23,
                              *(uint32_t*)&lo45, *(uint32_t*)&lo67);
        *(uint4*)(smem + SM_A + sw_off(r, c))      = hk;
        *(uint4*)(smem + SM_A + sw_off(r, c + 16)) = lk;
    }

    // ---- prefetch B subtile 0 (rows already [eh|el] segmented in gmem) ----
    {
        const uint32_t b0 = sb + SM_B0;
#pragma unroll
        for (int k = 0; k < 4; k++) {
            int id = tid + k * NTHREADS;       // 0..1023 chunks (32 rows x 32)
            int r = id >> 5, ci = id & 31;
            cp16(b0 + sw_off(r, ci), g_esplit + (size_t)r * K2 + ci * 8);
        }
        cp_commit();
    }

    // per-warp geometry
    const int colhalf = w >> 2;               // 0/1: cols 0-15 / 16-31 of subtile
    const int mrow0   = (w & 3) * 32;         // rows of this warp
    const int arow_l  = (l & 15);
    const int ag      = (l >> 4);             // 0/1 -> k-chunk offset
    const int brow    = colhalf * 16 + ((l >> 4) << 3) + (l & 7);
    const int bg      = (l >> 3) & 1;

    float bestv[4]; int besti[4];
#pragma unroll
    for (int i = 0; i < 4; i++) { bestv[i] = -FLT_MAX; besti[i] = 0; }

    for (int s = 0; s < NSUB; s++) {
        // prefetch next subtile into the other buffer
        if (s + 1 < NSUB) {
            const uint32_t bn = sb + (((s + 1) & 1) ? SM_B1 : SM_B0);
#pragma unroll
            for (int k = 0; k < 4; k++) {
                int id = tid + k * NTHREADS;
                int r = id >> 5, ci = id & 31;
                cp16(bn + sw_off(r, ci),
                     g_esplit + ((size_t)(s + 1) * SUBN + r) * K2 + ci * 8);
            }
            cp_commit();
            cp_wait1();
        } else {
            cp_wait0();
        }
        __syncthreads();   // subtile s visible to all; prior compute done before overwrite

        const uint32_t bbase = sb + ((s & 1) ? SM_B1 : SM_B0);

        float c[2][2][4];
#pragma unroll
        for (int mt = 0; mt < 2; mt++)
#pragma unroll
            for (int nt = 0; nt < 2; nt++)
#pragma unroll
                for (int i = 0; i < 4; i++) c[mt][nt][i] = 0.f;

        // fused 3-term split per kt: xh*eh + xl*eh + xh*el  (xl*el ~ 2^-22, dropped)
        // 6 LDSM + 12 MMA per kt (fragments loaded once, reused across terms)
#pragma unroll
        for (int kt = 0; kt < 8; kt++) {
            uint32_t aH0[4], aH1[4], aL0[4], bH[4], bL[4];
            const int ck = kt * 2;
            ldsm4(aH0, sb + SM_A + sw_off(mrow0 + arow_l,      ck + ag));
            ldsm4(aH1, sb + SM_A + sw_off(mrow0 + 16 + arow_l, ck + ag));
            ldsm4(bH, bbase + sw_off(brow, ck + bg));
            mma16816(c[0][0], aH0, bH[0], bH[1]);
            mma16816(c[0][1], aH0, bH[2], bH[3]);
            mma16816(c[1][0], aH1, bH[0], bH[1]);
            mma16816(c[1][1], aH1, bH[2], bH[3]);
            ldsm4(aL0, sb + SM_A + sw_off(mrow0 + arow_l,      16 + ck + ag));
            ldsm4(bL, bbase + sw_off(brow, 16 + ck + bg));
            mma16816(c[0][0], aL0, bH[0], bH[1]);
            mma16816(c[0][1], aL0, bH[2], bH[3]);
            mma16816(c[0][0], aH0, bL[0], bL[1]);
            mma16816(c[0][1], aH0, bL[2], bL[3]);
            ldsm4(aL0, sb + SM_A + sw_off(mrow0 + 16 + arow_l, 16 + ck + ag)); // reuse regs for aL1
            mma16816(c[1][0], aL0, bH[0], bH[1]);
            mma16816(c[1][1], aL0, bH[2], bH[3]);
            mma16816(c[1][0], aH1, bL[0], bL[1]);
            mma16816(c[1][1], aH1, bL[2], bL[3]);
        }

        // ---- score + running argmax (ascending col => first max wins) ----
        {
            int col0 = s * SUBN + colhalf * 16 + (l & 3) * 2;
            float2 eA = *(const float2*)(e2s + col0);
            float2 eB = *(const float2*)(e2s + col0 + 8);
#pragma unroll
            for (int mt = 0; mt < 2; mt++)
#pragma unroll
                for (int hh = 0; hh < 2; hh++) {
                    int sl = mt * 2 + hh;
                    float v0 = fmaf(2.f, c[mt][0][hh * 2 + 0], -eA.x);
                    float v1 = fmaf(2.f, c[mt][0][hh * 2 + 1], -eA.y);
                    float v2 = fmaf(2.f, c[mt][1][hh * 2 + 0], -eB.x);
                    float v3 = fmaf(2.f, c[mt][1][hh * 2 + 1], -eB.y);
                    if (v0 > bestv[sl]) { bestv[sl] = v0; besti[sl] = col0; }
                    if (v1 > bestv[sl]) { bestv[sl] = v1; besti[sl] = col0 + 1; }
                    if (v2 > bestv[sl]) { bestv[sl] = v2; besti[sl] = col0 + 8; }
                    if (v3 > bestv[sl]) { bestv[sl] = v3; besti[sl] = col0 + 9; }
                }
        }
        __syncthreads();   // compute done before next prefetch overwrites this buffer
    }

    // ---- cross-warp/lane argmax reduction ----
    float* redv = (float*)(smem + SM_REDV);
    int*   redi = (int*)(smem + SM_REDI);
    int*   fIdx = (int*)(smem + SM_FIDX);
#pragma unroll
    for (int mt = 0; mt < 2; mt++)
#pragma unroll
        for (int hh = 0; hh < 2; hh++) {
            int sl  = mt * 2 + hh;
            int row = mrow0 + mt * 16 + hh * 8 + (l >> 2);
            int cd  = colhalf * 4 + (l & 3);
            redv[row * 8 + cd] = bestv[sl];
            redi[row * 8 + cd] = besti[sl];
        }
    __syncthreads();
    if (tid < TM) {
        float bv = redv[tid * 8]; int bi = redi[tid * 8];
#pragma unroll
        for (int cd = 1; cd < 8; cd++) {
            float v = redv[tid * 8 + cd]; int ii = redi[tid * 8 + cd];
            if (v > bv || (v == bv && ii < bi)) { bv = v; bi = ii; }
        }
        fIdx[tid] = bi;
        int rg = rowbase + tid;
        if (out_idx != nullptr && rg < nrows) out_idx[rg] = (float)bi;
    }
    __syncthreads();

    // ---- gather: quantize = embed[idx] (bitwise-exact fp32 copy) ----
    for (int i = tid; i < TM * (DIM / 4); i += NTHREADS) {
        int r = i >> 5, c4 = (i & 31) << 2;
        int rg = rowbase + r;
        if (rg < nrows) {
            float4 v = *(const float4*)(embed + (size_t)fIdx[r] * DIM + c4);
            *(float4*)(out_q + (size_t)rg * DIM + c4) = v;
        }
    }
}

__global__ void fill_kernel(float* p, long long n) {
    long long i = (long long)blockIdx.x * blockDim.x + threadIdx.x;
    if (i < n) p[i] = 0.f;
}

// ---------------------------------------------------------------- launch
extern "C" void kernel_launch(void* const* d_in, const int* in_sizes, int n_in,
                              void* d_out, int out_size) {
    int xi = 0, ei = 1;
    if (n_in >= 2 && in_sizes[1] > in_sizes[0]) { xi = 1; ei = 0; }
    const float* x     = (const float*)d_in[xi];
    const float* embed = (const float*)d_in[ei];
    int nrows = in_sizes[xi] / DIM;

    float* out_q = (float*)d_out;
    long long ND = (long long)nrows * DIM;
    bool widx = ((long long)out_size >= ND + nrows);
    float* out_idx = widx ? out_q + ND : nullptr;

    prep_kernel<<<(KCODES * 32 + 255) / 256, 256>>>(embed);

    cudaFuncSetAttribute(vq_mma_kernel, cudaFuncAttributeMaxDynamicSharedMemorySize, SMEM_TOTAL);
    vq_mma_kernel<<<(nrows + TM - 1) / TM, NTHREADS, SMEM_TOTAL>>>(x, embed, out_q, out_idx, nrows);

    long long covered = ND + (widx ? nrows : 0);
    long long tail = (long long)out_size - covered;
    if (tail > 0)
        fill_kernel<<<(int)((tail + 255) / 256), 256>>>(out_q + covered, tail);
}

// round 11
// speedup vs baseline: 3.1428x; 1.0110x over previous
#include <cuda_runtime.h>
#include <cuda_fp16.h>
#include <cstdint>
#include <cfloat>

#define DIM      128
#define K2       256                 // halfs per row: [hi(128) | lo(128)]
#define KCODES   1024
#define TM       128                 // rows per CTA
#define SUBN     32                  // codes per subtile
#define NSUB     (KCODES / SUBN)
#define NTHREADS 256

// ---- smem byte offsets ----
#define SM_A     0                   // 128 rows x 512B (swizzled)      = 65536
#define SM_B0    65536               // 32 rows x 512B                  = 16384
#define SM_B1    81920               //                                 = 16384
#define SM_E2    98304               // 1024 floats                     = 4096
#define SM_REDV  102400              // 128*8 floats                    = 4096
#define SM_REDI  106496              // 128*8 ints                      = 4096
#define SM_FIDX  110592              // 128 ints                        = 512
#define SMEM_TOTAL 111104

__device__ float  g_e2[KCODES];
__device__ __half g_esplit[KCODES * K2];   // per code: [eh(128) | el(128)]

// ---------------------------------------------------------------- helpers
__device__ __forceinline__ uint32_t smem_u32(const void* p) {
    uint32_t a;
    asm("{ .reg .u64 t; cvta.to.shared.u64 t, %1; cvt.u32.u64 %0, t; }" : "=r"(a) : "l"(p));
    return a;
}
// swizzled byte offset: row-major 512B rows, 16B chunks XOR'd by row&7
__device__ __forceinline__ uint32_t sw_off(int row, int chunk) {
    return (uint32_t)(row * 512) + (uint32_t)(((chunk ^ (row & 7)) << 4));
}
__device__ __forceinline__ void ldsm4(uint32_t* r, uint32_t a) {
    asm volatile("ldmatrix.sync.aligned.m8n8.x4.shared.b16 {%0,%1,%2,%3}, [%4];"
                 : "=r"(r[0]), "=r"(r[1]), "=r"(r[2]), "=r"(r[3]) : "r"(a));
}
__device__ __forceinline__ void mma16816(float* c, const uint32_t* a, uint32_t b0, uint32_t b1) {
    asm volatile("mma.sync.aligned.m16n8k16.row.col.f32.f16.f16.f32 "
                 "{%0,%1,%2,%3}, {%4,%5,%6,%7}, {%8,%9}, {%0,%1,%2,%3};"
                 : "+f"(c[0]), "+f"(c[1]), "+f"(c[2]), "+f"(c[3])
                 : "r"(a[0]), "r"(a[1]), "r"(a[2]), "r"(a[3]), "r"(b0), "r"(b1));
}
__device__ __forceinline__ void cp16(uint32_t dst, const void* src) {
    asm volatile("cp.async.cg.shared.global [%0], [%1], 16;"
                 :: "r"(dst), "l"(__cvta_generic_to_global(src)) : "memory");
}
__device__ __forceinline__ void cp_commit() { asm volatile("cp.async.commit_group;" ::: "memory"); }
__device__ __forceinline__ void cp_wait1()  { asm volatile("cp.async.wait_group 1;" ::: "memory"); }
__device__ __forceinline__ void cp_wait0()  { asm volatile("cp.async.wait_group 0;" ::: "memory"); }

// ---------------------------------------------------------------- prep
// One warp per code: lane-parallel e2 (shuffle reduce) + fp16 hi/lo split.
__global__ void prep_kernel(const float* __restrict__ embed) {
    int gw   = (blockIdx.x * blockDim.x + threadIdx.x) >> 5;   // code id
    int lane = threadIdx.x & 31;
    if (gw >= KCODES) return;
    float4 v = *(const float4*)(embed + (size_t)gw * DIM + lane * 4);
    float s = fmaf(v.x, v.x, fmaf(v.y, v.y, fmaf(v.z, v.z, v.w * v.w)));
#pragma unroll
    for (int o = 16; o; o >>= 1) s += __shfl_xor_sync(0xFFFFFFFFu, s, o);
    if (lane == 0) g_e2[gw] = s;

    __half h0 = __float2half_rn(v.x), h1 = __float2half_rn(v.y),
           h2 = __float2half_rn(v.z), h3 = __float2half_rn(v.w);
    __half2 hiA = __halves2half2(h0, h1), hiB = __halves2half2(h2, h3);
    __half2 loA = __halves2half2(__float2half_rn(v.x - __half2float(h0)),
                                 __float2half_rn(v.y - __half2float(h1)));
    __half2 loB = __halves2half2(__float2half_rn(v.z - __half2float(h2)),
                                 __float2half_rn(v.w - __half2float(h3)));
    uint2 hk = make_uint2(*(uint32_t*)&hiA, *(uint32_t*)&hiB);
    uint2 lk = make_uint2(*(uint32_t*)&loA, *(uint32_t*)&loB);
    *(uint2*)(g_esplit + (size_t)gw * K2 + lane * 4)       = hk;
    *(uint2*)(g_esplit + (size_t)gw * K2 + 128 + lane * 4) = lk;
}

// ---------------------------------------------------------------- main
__global__ __launch_bounds__(NTHREADS, 2)
void vq_mma_kernel(const float* __restrict__ x, const float* __restrict__ embed,
                   float* __restrict__ out_q, float* __restrict__ out_idx, int nrows)
{
    extern __shared__ char smem[];
    const uint32_t sb = smem_u32(smem);
    const int tid  = threadIdx.x;
    const int w    = tid >> 5;
    const int l    = tid & 31;
    const int rowbase = blockIdx.x * TM;

    // e2 -> smem
    float* e2s = (float*)(smem + SM_E2);
    for (int i = tid; i < KCODES; i += NTHREADS) e2s[i] = g_e2[i];

    // ---- A tile: load x, fp16 hi/lo split into segments, swizzled store ----
    // chunk c (0..15) = dims 8c..8c+7 of hi; chunk c+16 = same dims of lo
#pragma unroll 2
    for (int it = 0; it < 8; it++) {
        int i = tid + it * NTHREADS;          // 0..2047
        int r = i >> 4, c = i & 15;           // row, dim-chunk (8 dims)
        int rg = rowbase + r; if (rg >= nrows) rg = nrows - 1;
        const float* xp = x + (size_t)rg * DIM + c * 8;
        float4 v0 = *(const float4*)(xp);
        float4 v1 = *(const float4*)(xp + 4);
        __half h0 = __float2half_rn(v0.x), h1 = __float2half_rn(v0.y),
               h2 = __float2half_rn(v0.z), h3 = __float2half_rn(v0.w),
               h4 = __float2half_rn(v1.x), h5 = __float2half_rn(v1.y),
               h6 = __float2half_rn(v1.z), h7 = __float2half_rn(v1.w);
        __half2 hi01 = __halves2half2(h0, h1), hi23 = __halves2half2(h2, h3);
        __half2 hi45 = __halves2half2(h4, h5), hi67 = __halves2half2(h6, h7);
        __half2 lo01 = __halves2half2(__float2half_rn(v0.x - __half2float(h0)),
                                      __float2half_rn(v0.y - __half2float(h1)));
        __half2 lo23 = __halves2half2(__float2half_rn(v0.z - __half2float(h2)),
                                      __float2half_rn(v0.w - __half2float(h3)));
        __half2 lo45 = __halves2half2(__float2half_rn(v1.x - __half2float(h4)),
                                      __float2half_rn(v1.y - __half2float(h5)));
        __half2 lo67 = __halves2half2(__float2half_rn(v1.z - __half2float(h6)),
                                      __float2half_rn(v1.w - __half2float(h7)));
        uint4 hk = make_uint4(*(uint32_t*)&hi01, *(uint32_t*)&hi23,
                              *(uint32_t*)&hi45, *(uint32_t*)&hi67);
        uint4 lk = make_uint4(*(uint32_t*)&lo01, *(uint32_t*)&lo23,
                              *(uint32_t*)&lo45, *(uint32_t*)&lo67);
        *(uint4*)(smem + SM_A + sw_off(r, c))      = hk;
        *(uint4*)(smem + SM_A + sw_off(r, c + 16)) = lk;
    }

    // ---- prefetch B subtile 0 (rows already [eh|el] segmented in gmem) ----
    {
        const uint32_t b0 = sb + SM_B0;
#pragma unroll
        for (int k = 0; k < 4; k++) {
            int id = tid + k * NTHREADS;       // 0..1023 chunks (32 rows x 32)
            int r = id >> 5, ci = id & 31;
            cp16(b0 + sw_off(r, ci), g_esplit + (size_t)r * K2 + ci * 8);
        }
        cp_commit();
    }

    // per-warp geometry
    const int colhalf = w >> 2;               // 0/1: cols 0-15 / 16-31 of subtile
    const int mrow0   = (w & 3) * 32;         // rows of this warp
    const int arow_l  = (l & 15);
    const int ag      = (l >> 4);             // 0/1 -> k-chunk offset
    const int brow    = colhalf * 16 + ((l >> 4) << 3) + (l & 7);
    const int bg      = (l >> 3) & 1;
    const int rowA0   = mrow0 + arow_l;
    const int rowA1   = mrow0 + 16 + arow_l;

    float bestv[4]; int besti[4];
#pragma unroll
    for (int i = 0; i < 4; i++) { bestv[i] = -FLT_MAX; besti[i] = 0; }

    for (int s = 0; s < NSUB; s++) {
        // prefetch next subtile into the other buffer
        if (s + 1 < NSUB) {
            const uint32_t bn = sb + (((s + 1) & 1) ? SM_B1 : SM_B0);
#pragma unroll
            for (int k = 0; k < 4; k++) {
                int id = tid + k * NTHREADS;
                int r = id >> 5, ci = id & 31;
                cp16(bn + sw_off(r, ci),
                     g_esplit + ((size_t)(s + 1) * SUBN + r) * K2 + ci * 8);
            }
            cp_commit();
            cp_wait1();
        } else {
            cp_wait0();
        }
        __syncthreads();   // subtile s visible to all; prior compute done before overwrite

        const uint32_t bbase = sb + ((s & 1) ? SM_B1 : SM_B0);

        float c[2][2][4];
#pragma unroll
        for (int mt = 0; mt < 2; mt++)
#pragma unroll
            for (int nt = 0; nt < 2; nt++)
#pragma unroll
                for (int i = 0; i < 4; i++) c[mt][nt][i] = 0.f;

        // fused 3-term split, software-pipelined fragments across kt:
        //   stage regs double-buffered; kt+1 LDSMs issue before kt MMAs so the
        //   crossbar streams while the tensor pipe drains.
        uint32_t fAH0[2][4], fAH1[2][4], fAL0[2][4], fAL1[2][4], fBH[2][4], fBL[2][4];
        // preload stage 0 (ck = 0)
        ldsm4(fAH0[0], sb + SM_A + sw_off(rowA0, ag));
        ldsm4(fAH1[0], sb + SM_A + sw_off(rowA1, ag));
        ldsm4(fBH[0],  bbase + sw_off(brow, bg));
        ldsm4(fAL0[0], sb + SM_A + sw_off(rowA0, 16 + ag));
        ldsm4(fAL1[0], sb + SM_A + sw_off(rowA1, 16 + ag));
        ldsm4(fBL[0],  bbase + sw_off(brow, 16 + bg));

#pragma unroll
        for (int kt = 0; kt < 8; kt++) {
            const int cur = kt & 1, nxt = cur ^ 1;
            if (kt < 7) {
                const int ck = (kt + 1) * 2;
                ldsm4(fAH0[nxt], sb + SM_A + sw_off(rowA0, ck + ag));
                ldsm4(fAH1[nxt], sb + SM_A + sw_off(rowA1, ck + ag));
                ldsm4(fBH[nxt],  bbase + sw_off(brow, ck + bg));
                ldsm4(fAL0[nxt], sb + SM_A + sw_off(rowA0, 16 + ck + ag));
                ldsm4(fAL1[nxt], sb + SM_A + sw_off(rowA1, 16 + ck + ag));
                ldsm4(fBL[nxt],  bbase + sw_off(brow, 16 + ck + bg));
            }
            // per-accumulator order t1 -> t2 -> t3 (identical numerics to R6)
            mma16816(c[0][0], fAH0[cur], fBH[cur][0], fBH[cur][1]);
            mma16816(c[0][1], fAH0[cur], fBH[cur][2], fBH[cur][3]);
            mma16816(c[1][0], fAH1[cur], fBH[cur][0], fBH[cur][1]);
            mma16816(c[1][1], fAH1[cur], fBH[cur][2], fBH[cur][3]);
            mma16816(c[0][0], fAL0[cur], fBH[cur][0], fBH[cur][1]);
            mma16816(c[0][1], fAL0[cur], fBH[cur][2], fBH[cur][3]);
            mma16816(c[1][0], fAL1[cur], fBH[cur][0], fBH[cur][1]);
            mma16816(c[1][1], fAL1[cur], fBH[cur][2], fBH[cur][3]);
            mma16816(c[0][0], fAH0[cur], fBL[cur][0], fBL[cur][1]);
            mma16816(c[0][1], fAH0[cur], fBL[cur][2], fBL[cur][3]);
            mma16816(c[1][0], fAH1[cur], fBL[cur][0], fBL[cur][1]);
            mma16816(c[1][1], fAH1[cur], fBL[cur][2], fBL[cur][3]);
        }

        // ---- score + running argmax (ascending col => first max wins) ----
        {
            int col0 = s * SUBN + colhalf * 16 + (l & 3) * 2;
            float2 eA = *(const float2*)(e2s + col0);
            float2 eB = *(const float2*)(e2s + col0 + 8);
#pragma unroll
            for (int mt = 0; mt < 2; mt++)
#pragma unroll
                for (int hh = 0; hh < 2; hh++) {
                    int sl = mt * 2 + hh;
                    float v0 = fmaf(2.f, c[mt][0][hh * 2 + 0], -eA.x);
                    float v1 = fmaf(2.f, c[mt][0][hh * 2 + 1], -eA.y);
                    float v2 = fmaf(2.f, c[mt][1][hh * 2 + 0], -eB.x);
                    float v3 = fmaf(2.f, c[mt][1][hh * 2 + 1], -eB.y);
                    if (v0 > bestv[sl]) { bestv[sl] = v0; besti[sl] = col0; }
                    if (v1 > bestv[sl]) { bestv[sl] = v1; besti[sl] = col0 + 1; }
                    if (v2 > bestv[sl]) { bestv[sl] = v2; besti[sl] = col0 + 8; }
                    if (v3 > bestv[sl]) { bestv[sl] = v3; besti[sl] = col0 + 9; }
                }
        }
        __syncthreads();   // compute done before next prefetch overwrites this buffer
    }

    // ---- cross-warp/lane argmax reduction ----
    float* redv = (float*)(smem + SM_REDV);
    int*   redi = (int*)(smem + SM_REDI);
    int*   fIdx = (int*)(smem + SM_FIDX);
#pragma unroll
    for (int mt = 0; mt < 2; mt++)
#pragma unroll
        for (int hh = 0; hh < 2; hh++) {
            int sl  = mt * 2 + hh;
            int row = mrow0 + mt * 16 + hh * 8 + (l >> 2);
            int cd  = colhalf * 4 + (l & 3);
            redv[row * 8 + cd] = bestv[sl];
            redi[row * 8 + cd] = besti[sl];
        }
    __syncthreads();
    if (tid < TM) {
        float bv = redv[tid * 8]; int bi = redi[tid * 8];
#pragma unroll
        for (int cd = 1; cd < 8; cd++) {
            float v = redv[tid * 8 + cd]; int ii = redi[tid * 8 + cd];
            if (v > bv || (v == bv && ii < bi)) { bv = v; bi = ii; }
        }
        fIdx[tid] = bi;
        int rg = rowbase + tid;
        if (out_idx != nullptr && rg < nrows) out_idx[rg] = (float)bi;
    }
    __syncthreads();

    // ---- gather: quantize = embed[idx] (bitwise-exact fp32 copy) ----
    for (int i = tid; i < TM * (DIM / 4); i += NTHREADS) {
        int r = i >> 5, c4 = (i & 31) << 2;
        int rg = rowbase + r;
        if (rg < nrows) {
            float4 v = *(const float4*)(embed + (size_t)fIdx[r] * DIM + c4);
            *(float4*)(out_q + (size_t)rg * DIM + c4) = v;
        }
    }
}

__global__ void fill_kernel(float* p, long long n) {
    long long i = (long long)blockIdx.x * blockDim.x + threadIdx.x;
    if (i < n) p[i] = 0.f;
}

// ---------------------------------------------------------------- launch
extern "C" void kernel_launch(void* const* d_in, const int* in_sizes, int n_in,
                              void* d_out, int out_size) {
    int xi = 0, ei = 1;
    if (n_in >= 2 && in_sizes[1] > in_sizes[0]) { xi = 1; ei = 0; }
    const float* x     = (const float*)d_in[xi];
    const float* embed = (const float*)d_in[ei];
    int nrows = in_sizes[xi] / DIM;

    float* out_q = (float*)d_out;
    long long ND = (long long)nrows * DIM;
    bool widx = ((long long)out_size >= ND + nrows);
    float* out_idx = widx ? out_q + ND : nullptr;

    prep_kernel<<<(KCODES * 32 + 255) / 256, 256>>>(embed);

    cudaFuncSetAttribute(vq_mma_kernel, cudaFuncAttributeMaxDynamicSharedMemorySize, SMEM_TOTAL);
    vq_mma_kernel<<<(nrows + TM - 1) / TM, NTHREADS, SMEM_TOTAL>>>(x, embed, out_q, out_idx, nrows);

    long long covered = ND + (widx ? nrows : 0);
    long long tail = (long long)out_size - covered;
    if (tail > 0)
        fill_kernel<<<(int)((tail + 255) / 256), 256>>>(out_q + covered, tail);
}